// round 3
// baseline (speedup 1.0000x reference)
#include <cuda_runtime.h>
#include <math_constants.h>

#define D_MODEL 1024
#define SEQ     2048
#define BATCH   2
#define HEADS   16
#define KD      64
#define MROWS   (BATCH*SEQ)   // 4096

// ---- scratch (device globals; no allocation in kernel_launch) ----
__device__ float g_Weff[3][D_MODEL*D_MODEL];     // fused Wq*Wqm, Wk*Wkm, Wv*Wvm
__device__ float g_beff[3][D_MODEL];             // fused biases
__device__ float g_QKV[3][MROWS*D_MODEL];        // Q, K, V projections

// =====================================================================
// Generic 128x128x16 fp32 GEMM body (N=K=1024), 256 threads, 8x8 microtile,
// double-buffered shared memory.
// =====================================================================
__device__ __forceinline__ void gemm_ldg(const float* __restrict__ A,
                                         const float* __restrict__ B,
                                         int bm, int bn, int kt, int tid,
                                         float4* aReg, float4* bReg)
{
#pragma unroll
    for (int c = 0; c < 2; c++) {
        int idx = c * 256 + tid;
        aReg[c] = *(const float4*)&A[(size_t)(bm + (idx >> 2)) * D_MODEL + kt * 16 + (idx & 3) * 4];
        bReg[c] = *(const float4*)&B[(size_t)(kt * 16 + (idx >> 5)) * D_MODEL + bn + (idx & 31) * 4];
    }
}

__device__ __forceinline__ void gemm_sts(float As[16][128], float Bs[16][128],
                                         int tid, const float4* aReg, const float4* bReg)
{
#pragma unroll
    for (int c = 0; c < 2; c++) {
        int idx = c * 256 + tid;
        int row = idx >> 2;
        int kq  = (idx & 3) * 4;
        As[kq + 0][row] = aReg[c].x;
        As[kq + 1][row] = aReg[c].y;
        As[kq + 2][row] = aReg[c].z;
        As[kq + 3][row] = aReg[c].w;
        *(float4*)&Bs[idx >> 5][(idx & 31) * 4] = bReg[c];
    }
}

template<bool BIAS>
__device__ __forceinline__ void gemm128(const float* __restrict__ A,
                                        const float* __restrict__ B,
                                        const float* __restrict__ bias,
                                        float* __restrict__ C)
{
    __shared__ float As[2][16][128];
    __shared__ float Bs[2][16][128];

    const int tid = threadIdx.x;
    const int tx = tid & 15, ty = tid >> 4;
    const int bm = blockIdx.y * 128, bn = blockIdx.x * 128;

    float4 aReg[2], bReg[2];

    gemm_ldg(A, B, bm, bn, 0, tid, aReg, bReg);
    gemm_sts(As[0], Bs[0], tid, aReg, bReg);
    __syncthreads();

    float acc[8][8] = {};

    const int NKT = D_MODEL / 16;   // 64
    for (int kt = 0; kt < NKT; kt++) {
        int buf = kt & 1;
        if (kt + 1 < NKT)
            gemm_ldg(A, B, bm, bn, kt + 1, tid, aReg, bReg);

#pragma unroll
        for (int k = 0; k < 16; k++) {
            float ar[8], br[8];
            *(float4*)&ar[0] = *(const float4*)&As[buf][k][ty * 8];
            *(float4*)&ar[4] = *(const float4*)&As[buf][k][ty * 8 + 4];
            *(float4*)&br[0] = *(const float4*)&Bs[buf][k][tx * 8];
            *(float4*)&br[4] = *(const float4*)&Bs[buf][k][tx * 8 + 4];
#pragma unroll
            for (int i = 0; i < 8; i++)
#pragma unroll
                for (int j = 0; j < 8; j++)
                    acc[i][j] += ar[i] * br[j];
        }

        if (kt + 1 < NKT) {
            gemm_sts(As[buf ^ 1], Bs[buf ^ 1], tid, aReg, bReg);
            __syncthreads();
        }
    }

    float bv[8];
    if (BIAS) {
        *(float4*)&bv[0] = *(const float4*)&bias[bn + tx * 8];
        *(float4*)&bv[4] = *(const float4*)&bias[bn + tx * 8 + 4];
    }
#pragma unroll
    for (int i = 0; i < 8; i++) {
        size_t row = (size_t)(bm + ty * 8 + i);
        float* cp = &C[row * D_MODEL + bn + tx * 8];
        float4 v0, v1;
        v0.x = acc[i][0] + (BIAS ? bv[0] : 0.f);
        v0.y = acc[i][1] + (BIAS ? bv[1] : 0.f);
        v0.z = acc[i][2] + (BIAS ? bv[2] : 0.f);
        v0.w = acc[i][3] + (BIAS ? bv[3] : 0.f);
        v1.x = acc[i][4] + (BIAS ? bv[4] : 0.f);
        v1.y = acc[i][5] + (BIAS ? bv[5] : 0.f);
        v1.z = acc[i][6] + (BIAS ? bv[6] : 0.f);
        v1.w = acc[i][7] + (BIAS ? bv[7] : 0.f);
        *(float4*)cp       = v0;
        *(float4*)(cp + 4) = v1;
    }
}

// =====================================================================
// Kernel 1: fused weights  Weff[z] = W1[z] @ W2[z]   (1024x1024x1024, z=0..2)
// =====================================================================
__global__ void fuse_weights_kernel(const float* __restrict__ Wq,
                                    const float* __restrict__ Wk,
                                    const float* __restrict__ Wv,
                                    const float* __restrict__ Wqm,
                                    const float* __restrict__ Wkm,
                                    const float* __restrict__ Wvm)
{
    int z = blockIdx.z;
    const float* A = (z == 0) ? Wq  : (z == 1) ? Wk  : Wv;
    const float* B = (z == 0) ? Wqm : (z == 1) ? Wkm : Wvm;
    gemm128<false>(A, B, nullptr, g_Weff[z]);
}

// =====================================================================
// Kernel 2: fused bias  beff[z] = b1[z] @ W2[z] + b2[z]
// =====================================================================
__global__ void fuse_bias_kernel(const float* __restrict__ bq,
                                 const float* __restrict__ bk,
                                 const float* __restrict__ bv,
                                 const float* __restrict__ Wqm,
                                 const float* __restrict__ Wkm,
                                 const float* __restrict__ Wvm,
                                 const float* __restrict__ bqm,
                                 const float* __restrict__ bkm,
                                 const float* __restrict__ bvm)
{
    int z = blockIdx.y;
    int n = blockIdx.x * blockDim.x + threadIdx.x;
    const float* b1 = (z == 0) ? bq  : (z == 1) ? bk  : bv;
    const float* W  = (z == 0) ? Wqm : (z == 1) ? Wkm : Wvm;
    const float* b2 = (z == 0) ? bqm : (z == 1) ? bkm : bvm;
    float s = b2[n];
    for (int k = 0; k < D_MODEL; k++)
        s += b1[k] * W[(size_t)k * D_MODEL + n];
    g_beff[z][n] = s;
}

// =====================================================================
// Kernel 3: projections  QKV[z] = (z?y:x) @ Weff[z] + beff[z]   (4096x1024x1024)
// =====================================================================
__global__ void proj_kernel(const float* __restrict__ x, const float* __restrict__ y)
{
    int z = blockIdx.z;
    const float* A = (z == 0) ? x : y;
    gemm128<true>(A, g_Weff[z], g_beff[z], g_QKV[z]);
}

// =====================================================================
// Kernel 4: flash attention.  Grid (SEQ/64, HEADS, BATCH), 256 threads.
// 64x64 tiles, Kd=64, online softmax. smem: Qt/Kt (d-major, pad 4),
// Vs (natural), Ps.
// =====================================================================
__device__ __forceinline__ float f4get(const float4& v, int i)
{
    return (i == 0) ? v.x : (i == 1) ? v.y : (i == 2) ? v.z : v.w;
}

__global__ void attn_kernel(float* __restrict__ out)
{
    extern __shared__ float sm[];
    constexpr int LDP = 68;          // 64 + 4 pad (keeps float4 alignment)
    float* Qt = sm;                  // [64][68]  Qt[d][row]
    float* Kt = Qt + 64 * LDP;       // [64][68]  Kt[d][col]
    float* Vs = Kt + 64 * LDP;       // [64][68]  Vs[col][d]
    float* Ps = Vs + 64 * LDP;       // [64][68]  Ps[row][col]

    const int tid = threadIdx.x;
    const int tx = tid & 15, ty = tid >> 4;
    const int b = blockIdx.z, h = blockIdx.y;
    const int q0 = blockIdx.x * 64;

    const float* __restrict__ Q  = g_QKV[0];
    const float* __restrict__ Kg = g_QKV[1];
    const float* __restrict__ Vg = g_QKV[2];
    const size_t basebh = (size_t)b * SEQ * D_MODEL + (size_t)h * KD;

    // Load Q tile (transposed, pre-scaled by 1/sqrt(Kd))
#pragma unroll
    for (int c = 0; c < 4; c++) {
        int idx = c * 256 + tid;
        int row = idx >> 4;          // 0..63
        int dq  = idx & 15;          // 0..15
        float4 v = *(const float4*)&Q[basebh + (size_t)(q0 + row) * D_MODEL + dq * 4];
        Qt[(dq * 4 + 0) * LDP + row] = v.x * 0.125f;
        Qt[(dq * 4 + 1) * LDP + row] = v.y * 0.125f;
        Qt[(dq * 4 + 2) * LDP + row] = v.z * 0.125f;
        Qt[(dq * 4 + 3) * LDP + row] = v.w * 0.125f;
    }

    float m[4], l[4], o[4][4];
#pragma unroll
    for (int i = 0; i < 4; i++) {
        m[i] = -CUDART_INF_F;
        l[i] = 0.f;
#pragma unroll
        for (int j = 0; j < 4; j++) o[i][j] = 0.f;
    }

    for (int k0 = 0; k0 < SEQ; k0 += 64) {
        __syncthreads();   // Q stores visible (iter 0); prior PV reads complete
        // Load K (transposed) + V (natural)
#pragma unroll
        for (int c = 0; c < 4; c++) {
            int idx = c * 256 + tid;
            int row = idx >> 4;
            int dq  = idx & 15;
            size_t g = basebh + (size_t)(k0 + row) * D_MODEL + dq * 4;
            float4 kv = *(const float4*)&Kg[g];
            Kt[(dq * 4 + 0) * LDP + row] = kv.x;
            Kt[(dq * 4 + 1) * LDP + row] = kv.y;
            Kt[(dq * 4 + 2) * LDP + row] = kv.z;
            Kt[(dq * 4 + 3) * LDP + row] = kv.w;
            float4 vv = *(const float4*)&Vg[g];
            *(float4*)&Vs[row * LDP + dq * 4] = vv;
        }
        __syncthreads();

        // S = (Q/8) @ K^T  — 4x4 per thread
        float s[4][4] = {};
#pragma unroll
        for (int d4 = 0; d4 < 16; d4++) {
            float4 qa[4], kb[4];
#pragma unroll
            for (int u = 0; u < 4; u++) {
                qa[u] = *(const float4*)&Qt[(d4 * 4 + u) * LDP + ty * 4];
                kb[u] = *(const float4*)&Kt[(d4 * 4 + u) * LDP + tx * 4];
            }
#pragma unroll
            for (int u = 0; u < 4; u++)
#pragma unroll
                for (int i = 0; i < 4; i++)
#pragma unroll
                    for (int j = 0; j < 4; j++)
                        s[i][j] += f4get(qa[u], i) * f4get(kb[u], j);
        }

        // Online softmax (rows split across 16 lanes with same ty)
#pragma unroll
        for (int i = 0; i < 4; i++) {
            float mt = fmaxf(fmaxf(s[i][0], s[i][1]), fmaxf(s[i][2], s[i][3]));
#pragma unroll
            for (int off = 8; off; off >>= 1)
                mt = fmaxf(mt, __shfl_xor_sync(0xffffffffu, mt, off, 16));
            float mn = fmaxf(m[i], mt);
            float alpha = __expf(m[i] - mn);
            m[i] = mn;
            float rs = 0.f;
#pragma unroll
            for (int j = 0; j < 4; j++) {
                float p = __expf(s[i][j] - mn);
                s[i][j] = p;
                rs += p;
            }
#pragma unroll
            for (int off = 8; off; off >>= 1)
                rs += __shfl_xor_sync(0xffffffffu, rs, off, 16);
            l[i] = l[i] * alpha + rs;
#pragma unroll
            for (int j = 0; j < 4; j++) o[i][j] *= alpha;
        }

        // Stage P
#pragma unroll
        for (int i = 0; i < 4; i++)
            *(float4*)&Ps[(ty * 4 + i) * LDP + tx * 4] =
                make_float4(s[i][0], s[i][1], s[i][2], s[i][3]);
        __syncthreads();

        // O += P @ V
#pragma unroll
        for (int c4 = 0; c4 < 16; c4++) {
            float4 vb[4], pv[4];
#pragma unroll
            for (int u = 0; u < 4; u++)
                vb[u] = *(const float4*)&Vs[(c4 * 4 + u) * LDP + tx * 4];
#pragma unroll
            for (int i = 0; i < 4; i++)
                pv[i] = *(const float4*)&Ps[(ty * 4 + i) * LDP + c4 * 4];
#pragma unroll
            for (int i = 0; i < 4; i++)
#pragma unroll
                for (int u = 0; u < 4; u++) {
                    float p = f4get(pv[i], u);
                    o[i][0] += p * vb[u].x;
                    o[i][1] += p * vb[u].y;
                    o[i][2] += p * vb[u].z;
                    o[i][3] += p * vb[u].w;
                }
        }
    }

    // Normalize + write
#pragma unroll
    for (int i = 0; i < 4; i++) {
        float inv = 1.f / l[i];
        float4 r = make_float4(o[i][0] * inv, o[i][1] * inv, o[i][2] * inv, o[i][3] * inv);
        *(float4*)&out[basebh + (size_t)(q0 + ty * 4 + i) * D_MODEL + tx * 4] = r;
    }
}

// =====================================================================
// Host launcher
// =====================================================================
extern "C" void kernel_launch(void* const* d_in, const int* in_sizes, int n_in,
                              void* d_out, int out_size)
{
    const float* x   = (const float*)d_in[0];
    const float* y   = (const float*)d_in[1];
    const float* Wq  = (const float*)d_in[2];
    const float* bq  = (const float*)d_in[3];
    const float* Wk  = (const float*)d_in[4];
    const float* bk  = (const float*)d_in[5];
    const float* Wv  = (const float*)d_in[6];
    const float* bv  = (const float*)d_in[7];
    const float* Wqm = (const float*)d_in[8];
    const float* bqm = (const float*)d_in[9];
    const float* Wkm = (const float*)d_in[10];
    const float* bkm = (const float*)d_in[11];
    const float* Wvm = (const float*)d_in[12];
    const float* bvm = (const float*)d_in[13];
    float* out = (float*)d_out;

    fuse_weights_kernel<<<dim3(8, 8, 3), 256>>>(Wq, Wk, Wv, Wqm, Wkm, Wvm);
    fuse_bias_kernel<<<dim3(4, 3), 256>>>(bq, bk, bv, Wqm, Wkm, Wvm, bqm, bkm, bvm);
    proj_kernel<<<dim3(8, 32, 3), 256>>>(x, y);

    int smem = 4 * 64 * 68 * (int)sizeof(float);   // 69632 bytes
    cudaFuncSetAttribute(attn_kernel, cudaFuncAttributeMaxDynamicSharedMemorySize, smem);
    attn_kernel<<<dim3(SEQ / 64, HEADS, BATCH), 256, smem>>>(out);
}

// round 5
// speedup vs baseline: 1.2550x; 1.2550x over previous
#include <cuda_runtime.h>
#include <math_constants.h>
#include <cstdint>

#define D_MODEL 1024
#define SEQ     2048
#define BATCH   2
#define HEADS   16
#define KD      64
#define MROWS   (BATCH*SEQ)   // 4096

// ---- scratch (device globals; no allocation in kernel_launch) ----
__device__ float g_Weff[3][D_MODEL*D_MODEL];
__device__ float g_beff[3][D_MODEL];
__device__ float g_QKV[3][MROWS*D_MODEL];

// =====================================================================
// tf32 helpers
// =====================================================================
__device__ __forceinline__ uint32_t cvt_tf32(float f) {
    uint32_t r;
    asm("cvt.rna.tf32.f32 %0, %1;" : "=r"(r) : "f"(f));
    return r;
}

__device__ __forceinline__ void mma8(float* d, const uint32_t* a, const uint32_t* b) {
    asm volatile(
        "mma.sync.aligned.m16n8k8.row.col.f32.tf32.tf32.f32 "
        "{%0,%1,%2,%3}, {%4,%5,%6,%7}, {%8,%9}, {%0,%1,%2,%3};"
        : "+f"(d[0]), "+f"(d[1]), "+f"(d[2]), "+f"(d[3])
        : "r"(a[0]), "r"(a[1]), "r"(a[2]), "r"(a[3]), "r"(b[0]), "r"(b[1]));
}

// =====================================================================
// tf32 mma.sync GEMM: C[128,128] tile = A(MxK row) @ B(KxN row) [+bias]
// K = N = 1024, 256 threads (8 warps as 2x4 -> 64x32 warp tiles).
// SPLITS=1: plain tf32.  SPLITS=3: hi/lo split (near-fp32 accuracy).
// Double-buffered smem, register-staged global loads.
// =====================================================================
#define KC      32                 // K per stage
#define NSTG    (D_MODEL / KC)     // 32 stages
#define LDA     36                 // A smem stride (floats)
#define LDB     136                // B smem stride (floats)
#define ASZ     (128 * LDA)        // 4608 floats
#define BSZ     (KC * LDB)         // 4352 floats

template<int SPLITS, bool BIAS>
__device__ void gemm_mma(const float* __restrict__ A, const float* __restrict__ B,
                         const float* __restrict__ bias, float* __restrict__ C)
{
    extern __shared__ uint32_t sm[];
    // layout: Ahi[2][ASZ], (Alo[2][ASZ]), Bhi[2][BSZ], (Blo[2][BSZ])
    uint32_t* sAhi = sm;
    uint32_t* sAlo = sAhi + 2 * ASZ;                       // only if SPLITS==3
    uint32_t* sBhi = sAhi + 2 * ASZ * (SPLITS == 3 ? 2 : 1);
    uint32_t* sBlo = sBhi + 2 * BSZ;

    const int tid = threadIdx.x;
    const int wid = tid >> 5, lane = tid & 31;
    const int g = lane >> 2, c = lane & 3;
    const int wm = (wid & 1) * 64, wn = (wid >> 1) * 32;
    const int bm = blockIdx.y * 128, bn = blockIdx.x * 128;

    // ldg mapping
    const int ar = tid >> 1, acb = (tid & 1) * 16;          // A: row, col-base (4x float4)
    const int bk = tid >> 3, bn0 = (tid & 7) * 4;           // B: k-row, n-base (4x float4, stride 32)

    float4 va[4], vb[4];

    auto ldg_stage = [&](int kc) {
        const float* ag = A + (size_t)(bm + ar) * D_MODEL + kc + acb;
#pragma unroll
        for (int q = 0; q < 4; q++) va[q] = *(const float4*)(ag + q * 4);
        const float* bg = B + (size_t)(kc + bk) * D_MODEL + bn + bn0;
#pragma unroll
        for (int q = 0; q < 4; q++) vb[q] = *(const float4*)(bg + q * 32);
    };

    auto sts_stage = [&](int buf) {
        uint32_t* Ah = sAhi + buf * ASZ;
        uint32_t* Bh = sBhi + buf * BSZ;
#pragma unroll
        for (int q = 0; q < 4; q++) {
            int ai = ar * LDA + acb + q * 4;
            uint32_t h[4] = { cvt_tf32(va[q].x), cvt_tf32(va[q].y),
                              cvt_tf32(va[q].z), cvt_tf32(va[q].w) };
            *(uint4*)&Ah[ai] = *(uint4*)h;
            if (SPLITS == 3) {
                uint32_t l[4] = { cvt_tf32(va[q].x - __uint_as_float(h[0])),
                                  cvt_tf32(va[q].y - __uint_as_float(h[1])),
                                  cvt_tf32(va[q].z - __uint_as_float(h[2])),
                                  cvt_tf32(va[q].w - __uint_as_float(h[3])) };
                *(uint4*)&sAlo[buf * ASZ + ai] = *(uint4*)l;
            }
        }
#pragma unroll
        for (int q = 0; q < 4; q++) {
            int bi = bk * LDB + bn0 + q * 32;
            uint32_t h[4] = { cvt_tf32(vb[q].x), cvt_tf32(vb[q].y),
                              cvt_tf32(vb[q].z), cvt_tf32(vb[q].w) };
            *(uint4*)&Bh[bi] = *(uint4*)h;
            if (SPLITS == 3) {
                uint32_t l[4] = { cvt_tf32(vb[q].x - __uint_as_float(h[0])),
                                  cvt_tf32(vb[q].y - __uint_as_float(h[1])),
                                  cvt_tf32(vb[q].z - __uint_as_float(h[2])),
                                  cvt_tf32(vb[q].w - __uint_as_float(h[3])) };
                *(uint4*)&sBlo[buf * BSZ + bi] = *(uint4*)l;
            }
        }
    };

    float acc[4][4][4] = {};   // [mi][ni][reg]

    ldg_stage(0);
    sts_stage(0);
    __syncthreads();

    for (int s = 0; s < NSTG; s++) {
        const int buf = s & 1;
        if (s + 1 < NSTG) ldg_stage((s + 1) * KC);

        const uint32_t* Ah = sAhi + buf * ASZ;
        const uint32_t* Bh = sBhi + buf * BSZ;
        const uint32_t* Al = sAlo + buf * ASZ;
        const uint32_t* Bl = sBlo + buf * BSZ;

#pragma unroll
        for (int ks = 0; ks < 4; ks++) {
            const int k0 = ks * 8;
            uint32_t af[4][4], bf[4][2];
#pragma unroll
            for (int mi = 0; mi < 4; mi++) {
                int R = wm + mi * 16 + g;
                af[mi][0] = Ah[R * LDA + k0 + c];
                af[mi][1] = Ah[(R + 8) * LDA + k0 + c];
                af[mi][2] = Ah[R * LDA + k0 + c + 4];
                af[mi][3] = Ah[(R + 8) * LDA + k0 + c + 4];
            }
#pragma unroll
            for (int ni = 0; ni < 4; ni++) {
                int N0 = wn + ni * 8 + g;
                bf[ni][0] = Bh[(k0 + c) * LDB + N0];
                bf[ni][1] = Bh[(k0 + c + 4) * LDB + N0];
            }
#pragma unroll
            for (int mi = 0; mi < 4; mi++)
#pragma unroll
                for (int ni = 0; ni < 4; ni++)
                    mma8(acc[mi][ni], af[mi], bf[ni]);

            if (SPLITS == 3) {
                uint32_t afl[4][4], bfl[4][2];
#pragma unroll
                for (int mi = 0; mi < 4; mi++) {
                    int R = wm + mi * 16 + g;
                    afl[mi][0] = Al[R * LDA + k0 + c];
                    afl[mi][1] = Al[(R + 8) * LDA + k0 + c];
                    afl[mi][2] = Al[R * LDA + k0 + c + 4];
                    afl[mi][3] = Al[(R + 8) * LDA + k0 + c + 4];
                }
#pragma unroll
                for (int ni = 0; ni < 4; ni++) {
                    int N0 = wn + ni * 8 + g;
                    bfl[ni][0] = Bl[(k0 + c) * LDB + N0];
                    bfl[ni][1] = Bl[(k0 + c + 4) * LDB + N0];
                }
#pragma unroll
                for (int mi = 0; mi < 4; mi++)
#pragma unroll
                    for (int ni = 0; ni < 4; ni++) {
                        mma8(acc[mi][ni], af[mi], bfl[ni]);
                        mma8(acc[mi][ni], afl[mi], bf[ni]);
                    }
            }
        }

        if (s + 1 < NSTG) {
            sts_stage(buf ^ 1);
            __syncthreads();
        }
    }

    // epilogue: direct gmem stores (float2 pairs; 4 lanes cover one 32B sector)
#pragma unroll
    for (int mi = 0; mi < 4; mi++) {
        int r0 = bm + wm + mi * 16 + g;
#pragma unroll
        for (int ni = 0; ni < 4; ni++) {
            int col = bn + wn + ni * 8 + c * 2;
            float b0 = BIAS ? bias[col] : 0.f;
            float b1 = BIAS ? bias[col + 1] : 0.f;
            *(float2*)&C[(size_t)r0 * D_MODEL + col] =
                make_float2(acc[mi][ni][0] + b0, acc[mi][ni][1] + b1);
            *(float2*)&C[(size_t)(r0 + 8) * D_MODEL + col] =
                make_float2(acc[mi][ni][2] + b0, acc[mi][ni][3] + b1);
        }
    }
}

// =====================================================================
// GEMM wrapper kernels
// =====================================================================
__global__ void __launch_bounds__(256, 1)
fuse_weights_mma(const float* __restrict__ Wq, const float* __restrict__ Wk,
                 const float* __restrict__ Wv, const float* __restrict__ Wqm,
                 const float* __restrict__ Wkm, const float* __restrict__ Wvm)
{
    int z = blockIdx.z;
    const float* A = (z == 0) ? Wq  : (z == 1) ? Wk  : Wv;
    const float* B = (z == 0) ? Wqm : (z == 1) ? Wkm : Wvm;
    gemm_mma<3, false>(A, B, nullptr, g_Weff[z]);
}

__global__ void __launch_bounds__(256, 1)
proj_mma(const float* __restrict__ x, const float* __restrict__ y)
{
    int z = blockIdx.z;
    const float* A = (z == 0) ? x : y;
    gemm_mma<1, true>(A, g_Weff[z], g_beff[z], g_QKV[z]);
}

// =====================================================================
// fused bias (tiny, fp32)
// =====================================================================
__global__ void fuse_bias_kernel(const float* __restrict__ bq, const float* __restrict__ bk,
                                 const float* __restrict__ bv, const float* __restrict__ Wqm,
                                 const float* __restrict__ Wkm, const float* __restrict__ Wvm,
                                 const float* __restrict__ bqm, const float* __restrict__ bkm,
                                 const float* __restrict__ bvm)
{
    int z = blockIdx.y;
    int n = blockIdx.x * blockDim.x + threadIdx.x;
    const float* b1 = (z == 0) ? bq  : (z == 1) ? bk  : bv;
    const float* W  = (z == 0) ? Wqm : (z == 1) ? Wkm : Wvm;
    const float* b2 = (z == 0) ? bqm : (z == 1) ? bkm : bvm;
    float s = b2[n];
    for (int k = 0; k < D_MODEL; k++)
        s += b1[k] * W[(size_t)k * D_MODEL + n];
    g_beff[z][n] = s;
}

// =====================================================================
// flash attention (fp32 SIMT, unchanged from passing baseline)
// =====================================================================
__device__ __forceinline__ float f4get(const float4& v, int i)
{
    return (i == 0) ? v.x : (i == 1) ? v.y : (i == 2) ? v.z : v.w;
}

__global__ void attn_kernel(float* __restrict__ out)
{
    extern __shared__ float smf[];
    constexpr int LDP = 68;
    float* Qt = smf;
    float* Kt = Qt + 64 * LDP;
    float* Vs = Kt + 64 * LDP;
    float* Ps = Vs + 64 * LDP;

    const int tid = threadIdx.x;
    const int tx = tid & 15, ty = tid >> 4;
    const int b = blockIdx.z, h = blockIdx.y;
    const int q0 = blockIdx.x * 64;

    const float* __restrict__ Q  = g_QKV[0];
    const float* __restrict__ Kg = g_QKV[1];
    const float* __restrict__ Vg = g_QKV[2];
    const size_t basebh = (size_t)b * SEQ * D_MODEL + (size_t)h * KD;

#pragma unroll
    for (int c = 0; c < 4; c++) {
        int idx = c * 256 + tid;
        int row = idx >> 4;
        int dq  = idx & 15;
        float4 v = *(const float4*)&Q[basebh + (size_t)(q0 + row) * D_MODEL + dq * 4];
        Qt[(dq * 4 + 0) * LDP + row] = v.x * 0.125f;
        Qt[(dq * 4 + 1) * LDP + row] = v.y * 0.125f;
        Qt[(dq * 4 + 2) * LDP + row] = v.z * 0.125f;
        Qt[(dq * 4 + 3) * LDP + row] = v.w * 0.125f;
    }

    float m[4], l[4], o[4][4];
#pragma unroll
    for (int i = 0; i < 4; i++) {
        m[i] = -CUDART_INF_F; l[i] = 0.f;
#pragma unroll
        for (int j = 0; j < 4; j++) o[i][j] = 0.f;
    }

    for (int k0 = 0; k0 < SEQ; k0 += 64) {
        __syncthreads();
#pragma unroll
        for (int c = 0; c < 4; c++) {
            int idx = c * 256 + tid;
            int row = idx >> 4;
            int dq  = idx & 15;
            size_t gg = basebh + (size_t)(k0 + row) * D_MODEL + dq * 4;
            float4 kv = *(const float4*)&Kg[gg];
            Kt[(dq * 4 + 0) * LDP + row] = kv.x;
            Kt[(dq * 4 + 1) * LDP + row] = kv.y;
            Kt[(dq * 4 + 2) * LDP + row] = kv.z;
            Kt[(dq * 4 + 3) * LDP + row] = kv.w;
            float4 vv = *(const float4*)&Vg[gg];
            *(float4*)&Vs[row * LDP + dq * 4] = vv;
        }
        __syncthreads();

        float s[4][4] = {};
#pragma unroll
        for (int d4 = 0; d4 < 16; d4++) {
            float4 qa[4], kb[4];
#pragma unroll
            for (int u = 0; u < 4; u++) {
                qa[u] = *(const float4*)&Qt[(d4 * 4 + u) * LDP + ty * 4];
                kb[u] = *(const float4*)&Kt[(d4 * 4 + u) * LDP + tx * 4];
            }
#pragma unroll
            for (int u = 0; u < 4; u++)
#pragma unroll
                for (int i = 0; i < 4; i++)
#pragma unroll
                    for (int j = 0; j < 4; j++)
                        s[i][j] += f4get(qa[u], i) * f4get(kb[u], j);
        }

#pragma unroll
        for (int i = 0; i < 4; i++) {
            float mt = fmaxf(fmaxf(s[i][0], s[i][1]), fmaxf(s[i][2], s[i][3]));
#pragma unroll
            for (int off = 8; off; off >>= 1)
                mt = fmaxf(mt, __shfl_xor_sync(0xffffffffu, mt, off, 16));
            float mn = fmaxf(m[i], mt);
            float alpha = __expf(m[i] - mn);
            m[i] = mn;
            float rs = 0.f;
#pragma unroll
            for (int j = 0; j < 4; j++) {
                float p = __expf(s[i][j] - mn);
                s[i][j] = p;
                rs += p;
            }
#pragma unroll
            for (int off = 8; off; off >>= 1)
                rs += __shfl_xor_sync(0xffffffffu, rs, off, 16);
            l[i] = l[i] * alpha + rs;
#pragma unroll
            for (int j = 0; j < 4; j++) o[i][j] *= alpha;
        }

#pragma unroll
        for (int i = 0; i < 4; i++)
            *(float4*)&Ps[(ty * 4 + i) * LDP + tx * 4] =
                make_float4(s[i][0], s[i][1], s[i][2], s[i][3]);
        __syncthreads();

#pragma unroll
        for (int c4 = 0; c4 < 16; c4++) {
            float4 vbv[4], pv[4];
#pragma unroll
            for (int u = 0; u < 4; u++)
                vbv[u] = *(const float4*)&Vs[(c4 * 4 + u) * LDP + tx * 4];
#pragma unroll
            for (int i = 0; i < 4; i++)
                pv[i] = *(const float4*)&Ps[(ty * 4 + i) * LDP + c4 * 4];
#pragma unroll
            for (int i = 0; i < 4; i++)
#pragma unroll
                for (int u = 0; u < 4; u++) {
                    float p = f4get(pv[i], u);
                    o[i][0] += p * vbv[u].x;
                    o[i][1] += p * vbv[u].y;
                    o[i][2] += p * vbv[u].z;
                    o[i][3] += p * vbv[u].w;
                }
        }
    }

#pragma unroll
    for (int i = 0; i < 4; i++) {
        float inv = 1.f / l[i];
        float4 r = make_float4(o[i][0] * inv, o[i][1] * inv, o[i][2] * inv, o[i][3] * inv);
        *(float4*)&out[basebh + (size_t)(q0 + ty * 4 + i) * D_MODEL + tx * 4] = r;
    }
}

// =====================================================================
// Host launcher
// =====================================================================
extern "C" void kernel_launch(void* const* d_in, const int* in_sizes, int n_in,
                              void* d_out, int out_size)
{
    const float* x   = (const float*)d_in[0];
    const float* y   = (const float*)d_in[1];
    const float* Wq  = (const float*)d_in[2];
    const float* bq  = (const float*)d_in[3];
    const float* Wk  = (const float*)d_in[4];
    const float* bk  = (const float*)d_in[5];
    const float* Wv  = (const float*)d_in[6];
    const float* bv  = (const float*)d_in[7];
    const float* Wqm = (const float*)d_in[8];
    const float* bqm = (const float*)d_in[9];
    const float* Wkm = (const float*)d_in[10];
    const float* bkm = (const float*)d_in[11];
    const float* Wvm = (const float*)d_in[12];
    const float* bvm = (const float*)d_in[13];
    float* out = (float*)d_out;

    const int smem1 = 2 * (ASZ + BSZ) * 4;        // 71680 B  (SPLITS=1)
    const int smem3 = 4 * (ASZ + BSZ) * 4;        // 143360 B (SPLITS=3)
    const int asmem = 4 * 64 * 68 * (int)sizeof(float);

    cudaFuncSetAttribute(fuse_weights_mma, cudaFuncAttributeMaxDynamicSharedMemorySize, smem3);
    cudaFuncSetAttribute(proj_mma, cudaFuncAttributeMaxDynamicSharedMemorySize, smem1);
    cudaFuncSetAttribute(attn_kernel, cudaFuncAttributeMaxDynamicSharedMemorySize, asmem);

    fuse_weights_mma<<<dim3(8, 8, 3), 256, smem3>>>(Wq, Wk, Wv, Wqm, Wkm, Wvm);
    fuse_bias_kernel<<<dim3(4, 3), 256>>>(bq, bk, bv, Wqm, Wkm, Wvm, bqm, bkm, bvm);
    proj_mma<<<dim3(8, 32, 3), 256, smem1>>>(x, y);

    attn_kernel<<<dim3(SEQ / 64, HEADS, BATCH), 256, asmem>>>(out);
}

// round 6
// speedup vs baseline: 2.2846x; 1.8203x over previous
#include <cuda_runtime.h>
#include <math_constants.h>
#include <cstdint>

#define D_MODEL 1024
#define SEQ     2048
#define BATCH   2
#define HEADS   16
#define KD      64
#define MROWS   (BATCH*SEQ)   // 4096

// ---- scratch (device globals; no allocation in kernel_launch) ----
__device__ float g_Weff[3][D_MODEL*D_MODEL];
__device__ float g_beff[3][D_MODEL];
__device__ float g_QKV[3][MROWS*D_MODEL];

// =====================================================================
// tf32 helpers
// =====================================================================
__device__ __forceinline__ uint32_t cvt_tf32(float f) {
    uint32_t r;
    asm("cvt.rna.tf32.f32 %0, %1;" : "=r"(r) : "f"(f));
    return r;
}

__device__ __forceinline__ void mma8(float* d, const uint32_t* a, const uint32_t* b) {
    asm volatile(
        "mma.sync.aligned.m16n8k8.row.col.f32.tf32.tf32.f32 "
        "{%0,%1,%2,%3}, {%4,%5,%6,%7}, {%8,%9}, {%0,%1,%2,%3};"
        : "+f"(d[0]), "+f"(d[1]), "+f"(d[2]), "+f"(d[3])
        : "r"(a[0]), "r"(a[1]), "r"(a[2]), "r"(a[3]), "r"(b[0]), "r"(b[1]));
}

// exp(x) for x <= 0 via exp2 range reduction + degree-5 poly. FMA-pipe only.
// rel err ~3e-6. Handles x = -inf (returns ~0).
__device__ __forceinline__ float expapprox(float x) {
    float t = fmaxf(x * 1.4426950408889634f, -126.f);
    float fn = t + 12582912.f;               // round-to-nearest int trick
    uint32_t ib = __float_as_uint(fn);
    float n = fn - 12582912.f;
    float f = t - n;                          // [-0.5, 0.5]
    float u = f * 0.6931471805599453f;
    float p = 1.f + u*(1.f + u*(0.5f + u*(0.16666667f + u*(0.041666668f + u*0.008333334f))));
    float s = __uint_as_float((ib + 127u - 0x4B400000u) << 23);
    return p * s;
}

// =====================================================================
// tf32 mma.sync GEMM (unchanged from passing R5 kernel)
// =====================================================================
#define KC      32
#define NSTG    (D_MODEL / KC)
#define LDA     36
#define LDB     136
#define ASZ     (128 * LDA)
#define BSZ     (KC * LDB)

template<int SPLITS, bool BIAS>
__device__ void gemm_mma(const float* __restrict__ A, const float* __restrict__ B,
                         const float* __restrict__ bias, float* __restrict__ C)
{
    extern __shared__ uint32_t sm[];
    uint32_t* sAhi = sm;
    uint32_t* sAlo = sAhi + 2 * ASZ;
    uint32_t* sBhi = sAhi + 2 * ASZ * (SPLITS == 3 ? 2 : 1);
    uint32_t* sBlo = sBhi + 2 * BSZ;

    const int tid = threadIdx.x;
    const int wid = tid >> 5, lane = tid & 31;
    const int g = lane >> 2, c = lane & 3;
    const int wm = (wid & 1) * 64, wn = (wid >> 1) * 32;
    const int bm = blockIdx.y * 128, bn = blockIdx.x * 128;

    const int ar = tid >> 1, acb = (tid & 1) * 16;
    const int bk = tid >> 3, bn0 = (tid & 7) * 4;

    float4 va[4], vb[4];

    auto ldg_stage = [&](int kc) {
        const float* ag = A + (size_t)(bm + ar) * D_MODEL + kc + acb;
#pragma unroll
        for (int q = 0; q < 4; q++) va[q] = *(const float4*)(ag + q * 4);
        const float* bg = B + (size_t)(kc + bk) * D_MODEL + bn + bn0;
#pragma unroll
        for (int q = 0; q < 4; q++) vb[q] = *(const float4*)(bg + q * 32);
    };

    auto sts_stage = [&](int buf) {
        uint32_t* Ah = sAhi + buf * ASZ;
        uint32_t* Bh = sBhi + buf * BSZ;
#pragma unroll
        for (int q = 0; q < 4; q++) {
            int ai = ar * LDA + acb + q * 4;
            uint32_t h[4] = { cvt_tf32(va[q].x), cvt_tf32(va[q].y),
                              cvt_tf32(va[q].z), cvt_tf32(va[q].w) };
            *(uint4*)&Ah[ai] = *(uint4*)h;
            if (SPLITS == 3) {
                uint32_t l[4] = { cvt_tf32(va[q].x - __uint_as_float(h[0])),
                                  cvt_tf32(va[q].y - __uint_as_float(h[1])),
                                  cvt_tf32(va[q].z - __uint_as_float(h[2])),
                                  cvt_tf32(va[q].w - __uint_as_float(h[3])) };
                *(uint4*)&sAlo[buf * ASZ + ai] = *(uint4*)l;
            }
        }
#pragma unroll
        for (int q = 0; q < 4; q++) {
            int bi = bk * LDB + bn0 + q * 32;
            uint32_t h[4] = { cvt_tf32(vb[q].x), cvt_tf32(vb[q].y),
                              cvt_tf32(vb[q].z), cvt_tf32(vb[q].w) };
            *(uint4*)&Bh[bi] = *(uint4*)h;
            if (SPLITS == 3) {
                uint32_t l[4] = { cvt_tf32(vb[q].x - __uint_as_float(h[0])),
                                  cvt_tf32(vb[q].y - __uint_as_float(h[1])),
                                  cvt_tf32(vb[q].z - __uint_as_float(h[2])),
                                  cvt_tf32(vb[q].w - __uint_as_float(h[3])) };
                *(uint4*)&sBlo[buf * BSZ + bi] = *(uint4*)l;
            }
        }
    };

    float acc[4][4][4] = {};

    ldg_stage(0);
    sts_stage(0);
    __syncthreads();

    for (int s = 0; s < NSTG; s++) {
        const int buf = s & 1;
        if (s + 1 < NSTG) ldg_stage((s + 1) * KC);

        const uint32_t* Ah = sAhi + buf * ASZ;
        const uint32_t* Bh = sBhi + buf * BSZ;
        const uint32_t* Al = sAlo + buf * ASZ;
        const uint32_t* Bl = sBlo + buf * BSZ;

#pragma unroll
        for (int ks = 0; ks < 4; ks++) {
            const int k0 = ks * 8;
            uint32_t af[4][4], bf[4][2];
#pragma unroll
            for (int mi = 0; mi < 4; mi++) {
                int R = wm + mi * 16 + g;
                af[mi][0] = Ah[R * LDA + k0 + c];
                af[mi][1] = Ah[(R + 8) * LDA + k0 + c];
                af[mi][2] = Ah[R * LDA + k0 + c + 4];
                af[mi][3] = Ah[(R + 8) * LDA + k0 + c + 4];
            }
#pragma unroll
            for (int ni = 0; ni < 4; ni++) {
                int N0 = wn + ni * 8 + g;
                bf[ni][0] = Bh[(k0 + c) * LDB + N0];
                bf[ni][1] = Bh[(k0 + c + 4) * LDB + N0];
            }
#pragma unroll
            for (int mi = 0; mi < 4; mi++)
#pragma unroll
                for (int ni = 0; ni < 4; ni++)
                    mma8(acc[mi][ni], af[mi], bf[ni]);

            if (SPLITS == 3) {
                uint32_t afl[4][4], bfl[4][2];
#pragma unroll
                for (int mi = 0; mi < 4; mi++) {
                    int R = wm + mi * 16 + g;
                    afl[mi][0] = Al[R * LDA + k0 + c];
                    afl[mi][1] = Al[(R + 8) * LDA + k0 + c];
                    afl[mi][2] = Al[R * LDA + k0 + c + 4];
                    afl[mi][3] = Al[(R + 8) * LDA + k0 + c + 4];
                }
#pragma unroll
                for (int ni = 0; ni < 4; ni++) {
                    int N0 = wn + ni * 8 + g;
                    bfl[ni][0] = Bl[(k0 + c) * LDB + N0];
                    bfl[ni][1] = Bl[(k0 + c + 4) * LDB + N0];
                }
#pragma unroll
                for (int mi = 0; mi < 4; mi++)
#pragma unroll
                    for (int ni = 0; ni < 4; ni++) {
                        mma8(acc[mi][ni], af[mi], bfl[ni]);
                        mma8(acc[mi][ni], afl[mi], bf[ni]);
                    }
            }
        }

        if (s + 1 < NSTG) {
            sts_stage(buf ^ 1);
            __syncthreads();
        }
    }

#pragma unroll
    for (int mi = 0; mi < 4; mi++) {
        int r0 = bm + wm + mi * 16 + g;
#pragma unroll
        for (int ni = 0; ni < 4; ni++) {
            int col = bn + wn + ni * 8 + c * 2;
            float b0 = BIAS ? bias[col] : 0.f;
            float b1 = BIAS ? bias[col + 1] : 0.f;
            *(float2*)&C[(size_t)r0 * D_MODEL + col] =
                make_float2(acc[mi][ni][0] + b0, acc[mi][ni][1] + b1);
            *(float2*)&C[(size_t)(r0 + 8) * D_MODEL + col] =
                make_float2(acc[mi][ni][2] + b0, acc[mi][ni][3] + b1);
        }
    }
}

__global__ void __launch_bounds__(256, 1)
fuse_weights_mma(const float* __restrict__ Wq, const float* __restrict__ Wk,
                 const float* __restrict__ Wv, const float* __restrict__ Wqm,
                 const float* __restrict__ Wkm, const float* __restrict__ Wvm)
{
    int z = blockIdx.z;
    const float* A = (z == 0) ? Wq  : (z == 1) ? Wk  : Wv;
    const float* B = (z == 0) ? Wqm : (z == 1) ? Wkm : Wvm;
    gemm_mma<3, false>(A, B, nullptr, g_Weff[z]);
}

__global__ void __launch_bounds__(256, 1)
proj_mma(const float* __restrict__ x, const float* __restrict__ y)
{
    int z = blockIdx.z;
    const float* A = (z == 0) ? x : y;
    gemm_mma<1, true>(A, g_Weff[z], g_beff[z], g_QKV[z]);
}

__global__ void fuse_bias_kernel(const float* __restrict__ bq, const float* __restrict__ bk,
                                 const float* __restrict__ bv, const float* __restrict__ Wqm,
                                 const float* __restrict__ Wkm, const float* __restrict__ Wvm,
                                 const float* __restrict__ bqm, const float* __restrict__ bkm,
                                 const float* __restrict__ bvm)
{
    int z = blockIdx.y;
    int n = blockIdx.x * blockDim.x + threadIdx.x;
    const float* b1 = (z == 0) ? bq  : (z == 1) ? bk  : bv;
    const float* W  = (z == 0) ? Wqm : (z == 1) ? Wkm : Wvm;
    const float* b2 = (z == 0) ? bqm : (z == 1) ? bkm : bvm;
    float s = b2[n];
    for (int k = 0; k < D_MODEL; k++)
        s += b1[k] * W[(size_t)k * D_MODEL + n];
    g_beff[z][n] = s;
}

// =====================================================================
// tf32 mma flash attention.
// Grid (SEQ/128, HEADS, BATCH) = (16,16,2), 256 threads (8 warps).
// Each warp: 16 q-rows. KV tiles of 64 keys. Q frags register-resident.
// smem: Kt[64][68], Vt[64][72], Pt[128][68] (Q staging then P tiles).
// exp via FMA-pipe polynomial (no MUFU bottleneck).
// =====================================================================
#define LDK 68
#define LDV 72
#define LDPT 68
#define ATT_SMEM ((64*LDK + 64*LDV + 128*LDPT) * 4)

__global__ void __launch_bounds__(256)
attn_mma(float* __restrict__ out)
{
    extern __shared__ uint32_t smu[];
    uint32_t* Kt = smu;                       // [64][68]
    uint32_t* Vt = smu + 64 * LDK;            // [64][72]
    uint32_t* Pt = smu + 64 * LDK + 64 * LDV; // [128][68]

    const int tid = threadIdx.x;
    const int wid = tid >> 5, lane = tid & 31;
    const int g = lane >> 2, c = lane & 3;
    const int b = blockIdx.z, h = blockIdx.y;
    const int q0 = blockIdx.x * 128;
    const int wr = wid * 16;

    const float* __restrict__ Q  = g_QKV[0];
    const float* __restrict__ Kg = g_QKV[1];
    const float* __restrict__ Vg = g_QKV[2];
    const size_t basebh = (size_t)b * SEQ * D_MODEL + (size_t)h * KD;

    // stage Q (scaled 1/8, tf32) into Pt
#pragma unroll
    for (int cc = 0; cc < 8; cc++) {
        int idx = cc * 256 + tid;
        int row = idx >> 4, dq = idx & 15;
        float4 v = *(const float4*)&Q[basebh + (size_t)(q0 + row) * D_MODEL + dq * 4];
        uint32_t w[4] = { cvt_tf32(v.x * 0.125f), cvt_tf32(v.y * 0.125f),
                          cvt_tf32(v.z * 0.125f), cvt_tf32(v.w * 0.125f) };
        *(uint4*)&Pt[row * LDPT + dq * 4] = *(uint4*)w;
    }
    __syncthreads();

    // Q fragments (resident for whole kernel)
    uint32_t qf[8][4];
#pragma unroll
    for (int kc = 0; kc < 8; kc++) {
        qf[kc][0] = Pt[(wr + g)     * LDPT + kc * 8 + c];
        qf[kc][1] = Pt[(wr + g + 8) * LDPT + kc * 8 + c];
        qf[kc][2] = Pt[(wr + g)     * LDPT + kc * 8 + c + 4];
        qf[kc][3] = Pt[(wr + g + 8) * LDPT + kc * 8 + c + 4];
    }

    float m0 = -CUDART_INF_F, m1 = -CUDART_INF_F, l0 = 0.f, l1 = 0.f;
    float oacc[8][4];
#pragma unroll
    for (int i = 0; i < 8; i++)
#pragma unroll
        for (int j = 0; j < 4; j++) oacc[i][j] = 0.f;

    for (int kv0 = 0; kv0 < SEQ; kv0 += 64) {
        __syncthreads();   // guards Pt (Q-frag reads, iter0) & Kt/Vt reuse
        // load K,V tiles (tf32)
#pragma unroll
        for (int cc = 0; cc < 4; cc++) {
            int idx = cc * 256 + tid;
            int row = idx >> 4, dq = idx & 15;
            size_t gg = basebh + (size_t)(kv0 + row) * D_MODEL + dq * 4;
            float4 kv = *(const float4*)&Kg[gg];
            uint32_t wk[4] = { cvt_tf32(kv.x), cvt_tf32(kv.y), cvt_tf32(kv.z), cvt_tf32(kv.w) };
            *(uint4*)&Kt[row * LDK + dq * 4] = *(uint4*)wk;
            float4 vv = *(const float4*)&Vg[gg];
            uint32_t wv[4] = { cvt_tf32(vv.x), cvt_tf32(vv.y), cvt_tf32(vv.z), cvt_tf32(vv.w) };
            *(uint4*)&Vt[row * LDV + dq * 4] = *(uint4*)wv;
        }
        __syncthreads();

        // S = Qs @ K^T
        float sacc[8][4];
#pragma unroll
        for (int i = 0; i < 8; i++)
#pragma unroll
            for (int j = 0; j < 4; j++) sacc[i][j] = 0.f;
#pragma unroll
        for (int nt = 0; nt < 8; nt++) {
#pragma unroll
            for (int kc = 0; kc < 8; kc++) {
                uint32_t bf[2];
                bf[0] = Kt[(nt * 8 + g) * LDK + kc * 8 + c];
                bf[1] = Kt[(nt * 8 + g) * LDK + kc * 8 + c + 4];
                mma8(sacc[nt], qf[kc], bf);
            }
        }

        // online softmax — rows r0 (regs 0,1), r1 (regs 2,3)
        float mt0 = sacc[0][0], mt1 = sacc[0][2];
#pragma unroll
        for (int nt = 0; nt < 8; nt++) {
            mt0 = fmaxf(mt0, fmaxf(sacc[nt][0], sacc[nt][1]));
            mt1 = fmaxf(mt1, fmaxf(sacc[nt][2], sacc[nt][3]));
        }
        mt0 = fmaxf(mt0, __shfl_xor_sync(0xffffffffu, mt0, 1));
        mt0 = fmaxf(mt0, __shfl_xor_sync(0xffffffffu, mt0, 2));
        mt1 = fmaxf(mt1, __shfl_xor_sync(0xffffffffu, mt1, 1));
        mt1 = fmaxf(mt1, __shfl_xor_sync(0xffffffffu, mt1, 2));

        float mn0 = fmaxf(m0, mt0), mn1 = fmaxf(m1, mt1);
        float a0 = expapprox(m0 - mn0), a1 = expapprox(m1 - mn1);
        m0 = mn0; m1 = mn1;

        float rs0 = 0.f, rs1 = 0.f;
#pragma unroll
        for (int nt = 0; nt < 8; nt++) {
            float p0 = expapprox(sacc[nt][0] - mn0);
            float p1 = expapprox(sacc[nt][1] - mn0);
            float p2 = expapprox(sacc[nt][2] - mn1);
            float p3 = expapprox(sacc[nt][3] - mn1);
            rs0 += p0 + p1;
            rs1 += p2 + p3;
            uint32_t w0[2] = { cvt_tf32(p0), cvt_tf32(p1) };
            uint32_t w1[2] = { cvt_tf32(p2), cvt_tf32(p3) };
            *(uint2*)&Pt[(wr + g)     * LDPT + nt * 8 + 2 * c] = *(uint2*)w0;
            *(uint2*)&Pt[(wr + g + 8) * LDPT + nt * 8 + 2 * c] = *(uint2*)w1;
        }
        rs0 += __shfl_xor_sync(0xffffffffu, rs0, 1);
        rs0 += __shfl_xor_sync(0xffffffffu, rs0, 2);
        rs1 += __shfl_xor_sync(0xffffffffu, rs1, 1);
        rs1 += __shfl_xor_sync(0xffffffffu, rs1, 2);
        l0 = l0 * a0 + rs0;
        l1 = l1 * a1 + rs1;
#pragma unroll
        for (int nt = 0; nt < 8; nt++) {
            oacc[nt][0] *= a0; oacc[nt][1] *= a0;
            oacc[nt][2] *= a1; oacc[nt][3] *= a1;
        }
        __syncwarp();   // P rows are warp-local

        // O += P @ V
#pragma unroll
        for (int kc = 0; kc < 8; kc++) {
            uint32_t pa[4];
            pa[0] = Pt[(wr + g)     * LDPT + kc * 8 + c];
            pa[1] = Pt[(wr + g + 8) * LDPT + kc * 8 + c];
            pa[2] = Pt[(wr + g)     * LDPT + kc * 8 + c + 4];
            pa[3] = Pt[(wr + g + 8) * LDPT + kc * 8 + c + 4];
#pragma unroll
            for (int dt = 0; dt < 8; dt++) {
                uint32_t vb[2];
                vb[0] = Vt[(kc * 8 + c)     * LDV + dt * 8 + g];
                vb[1] = Vt[(kc * 8 + c + 4) * LDV + dt * 8 + g];
                mma8(oacc[dt], pa, vb);
            }
        }
    }

    // epilogue
    float inv0 = 1.f / l0, inv1 = 1.f / l1;
#pragma unroll
    for (int dt = 0; dt < 8; dt++) {
        int col = dt * 8 + 2 * c;
        *(float2*)&out[basebh + (size_t)(q0 + wr + g) * D_MODEL + col] =
            make_float2(oacc[dt][0] * inv0, oacc[dt][1] * inv0);
        *(float2*)&out[basebh + (size_t)(q0 + wr + g + 8) * D_MODEL + col] =
            make_float2(oacc[dt][2] * inv1, oacc[dt][3] * inv1);
    }
}

// =====================================================================
// Host launcher
// =====================================================================
extern "C" void kernel_launch(void* const* d_in, const int* in_sizes, int n_in,
                              void* d_out, int out_size)
{
    const float* x   = (const float*)d_in[0];
    const float* y   = (const float*)d_in[1];
    const float* Wq  = (const float*)d_in[2];
    const float* bq  = (const float*)d_in[3];
    const float* Wk  = (const float*)d_in[4];
    const float* bk  = (const float*)d_in[5];
    const float* Wv  = (const float*)d_in[6];
    const float* bv  = (const float*)d_in[7];
    const float* Wqm = (const float*)d_in[8];
    const float* bqm = (const float*)d_in[9];
    const float* Wkm = (const float*)d_in[10];
    const float* bkm = (const float*)d_in[11];
    const float* Wvm = (const float*)d_in[12];
    const float* bvm = (const float*)d_in[13];
    float* out = (float*)d_out;

    const int smem1 = 2 * (ASZ + BSZ) * 4;
    const int smem3 = 4 * (ASZ + BSZ) * 4;

    cudaFuncSetAttribute(fuse_weights_mma, cudaFuncAttributeMaxDynamicSharedMemorySize, smem3);
    cudaFuncSetAttribute(proj_mma, cudaFuncAttributeMaxDynamicSharedMemorySize, smem1);
    cudaFuncSetAttribute(attn_mma, cudaFuncAttributeMaxDynamicSharedMemorySize, ATT_SMEM);

    fuse_weights_mma<<<dim3(8, 8, 3), 256, smem3>>>(Wq, Wk, Wv, Wqm, Wkm, Wvm);
    fuse_bias_kernel<<<dim3(4, 3), 256>>>(bq, bk, bv, Wqm, Wkm, Wvm, bqm, bkm, bvm);
    proj_mma<<<dim3(8, 32, 3), 256, smem1>>>(x, y);

    attn_mma<<<dim3(SEQ / 128, HEADS, BATCH), 256, ATT_SMEM>>>(out);
}